// round 1
// baseline (speedup 1.0000x reference)
#include <cuda_runtime.h>
#include <math.h>

// ---------------------------------------------------------------------------
// TConvDRAW: B=128, NZ=64, NCL=NCC=NCS=128, NA=8, ZH=16, STEPS=6
// Outputs (float32, concatenated): z_t[128*64*256], s_t[128*128*256],
//   c_ssm_t[128*128*256], kl[1], lpq[128]
// ---------------------------------------------------------------------------

#define PIX   256          // 16*16
#define BATCH 128
#define STEPS 6

// scratch offsets (in floats)
#define OFF_STATIC_Q 0u
#define OFF_STATIC_P 16777216u
#define OFF_GATES    33554432u
#define OFF_HP       50331648u
#define OFF_CP       54525952u
#define OFF_HQ       58720256u
#define OFF_CQ       62914560u
#define OFF_RQ       67108864u
#define OFF_RP       71303168u
#define OFF_Z        75497472u
#define OFF_KLB      77594624u
#define OFF_LPQB     77594752u
#define SCRATCH_N    77594880u

__device__ float g_scratch[SCRATCH_N];

// ---------------------------------------------------------------------------
// 5x5 SAME conv, fp32 direct, register-blocked.
// Input is a virtual channel-concat of up to 4 segments (avoids materializing
// concatenated tensors). Optional per-element base (precomputed static gates)
// and optional bias.
// Block: 256 threads. Each thread: 4 pixels (1x4 row strip) x 8 couts.
// Block covers 32 couts x 256 pixels of one batch image.
// grid = (cout/32, BATCH)
// ---------------------------------------------------------------------------
struct Seg { const float* p; int cin; int cioff; };
struct ConvArgs {
    Seg seg[4];
    int nseg;
    const float* W;      // [cout, cinTot, 5, 5]
    int cinTot;
    const float* bias;   // [cout] or null
    const float* base;   // [B, cout, 256] or null
    float* out;          // [B, cout, 256]
    int cout;
};

__global__ void __launch_bounds__(256, 2) conv5x5_kernel(ConvArgs a) {
    __shared__ float sp[20 * 21];   // padded input plane, stride 21 (conflict relief)
    __shared__ float sw[32 * 25];   // weights for 32 couts, current ci

    const int b      = blockIdx.y;
    const int coBase = blockIdx.x * 32;
    const int tid    = threadIdx.x;
    const int strip  = tid & 63;        // 0..63
    const int row    = strip >> 2;      // 0..15
    const int xb     = (strip & 3) << 2;// 0,4,8,12
    const int coG    = tid >> 6;        // 0..3

    float acc[8][4];
#pragma unroll
    for (int co = 0; co < 8; ++co)
#pragma unroll
        for (int px = 0; px < 4; ++px) acc[co][px] = 0.f;

    for (int s = 0; s < a.nseg; ++s) {
        const float* src  = a.seg[s].p + (size_t)b * a.seg[s].cin * PIX;
        const int    cin  = a.seg[s].cin;
        const int    coff = a.seg[s].cioff;
        for (int ci = 0; ci < cin; ++ci) {
            __syncthreads();
            // load padded input plane (zeros outside 16x16)
            for (int i = tid; i < 400; i += 256) {
                int r = i / 20 - 2;
                int c = i % 20 - 2;
                float v = 0.f;
                if ((unsigned)r < 16u && (unsigned)c < 16u)
                    v = src[ci * PIX + r * 16 + c];
                sp[(r + 2) * 21 + (c + 2)] = v;
            }
            // load 32x25 weights for this ci
            for (int i = tid; i < 800; i += 256) {
                int col = i / 25;
                int k   = i % 25;
                sw[i] = a.W[((size_t)(coBase + col) * a.cinTot + coff + ci) * 25 + k];
            }
            __syncthreads();

#pragma unroll
            for (int dy = 0; dy < 5; ++dy) {
                float xv[8];
#pragma unroll
                for (int j = 0; j < 8; ++j) xv[j] = sp[(row + dy) * 21 + xb + j];
#pragma unroll
                for (int co = 0; co < 8; ++co) {
                    const float* wp = &sw[(coG * 8 + co) * 25 + dy * 5];
#pragma unroll
                    for (int dx = 0; dx < 5; ++dx) {
                        float w = wp[dx];
#pragma unroll
                        for (int px = 0; px < 4; ++px)
                            acc[co][px] = fmaf(w, xv[px + dx], acc[co][px]);
                    }
                }
            }
        }
    }

    // epilogue
#pragma unroll
    for (int co = 0; co < 8; ++co) {
        const int c = coBase + coG * 8 + co;
        const size_t o = ((size_t)b * a.cout + c) * PIX + row * 16 + xb;
        float bias = a.bias ? a.bias[c] : 0.f;
#pragma unroll
        for (int px = 0; px < 4; ++px) {
            float v = acc[co][px] + bias;
            if (a.base) v += a.base[o + px];
            a.out[o + px] = v;
        }
    }
}

// ---------------------------------------------------------------------------
// LSTM pointwise update: gates [B,512,256] (i,f,o,g blocks of 128 ch each)
// total = B*128*256 = 4194304
// ---------------------------------------------------------------------------
__device__ __forceinline__ float sigmoidf_(float x) { return 1.f / (1.f + expf(-x)); }

__global__ void lstm_kernel(const float* __restrict__ gates,
                            const float* __restrict__ c_in,
                            float* __restrict__ h_out,
                            float* __restrict__ c_out) {
    int idx = blockIdx.x * blockDim.x + threadIdx.x;
    if (idx >= 4194304) return;
    int b = idx >> 15;        // / (128*256)
    int r = idx & 32767;
    size_t g0 = (size_t)b * 131072 + r;  // b*512*256 + ch*256 + pix
    float ig = gates[g0];
    float fg = gates[g0 + 32768];
    float og = gates[g0 + 65536];
    float gg = gates[g0 + 98304];
    float c  = sigmoidf_(fg) * c_in[idx] + sigmoidf_(ig) * tanhf(gg);
    c_out[idx] = c;
    h_out[idx] = sigmoidf_(og) * tanhf(c);
}

// ---------------------------------------------------------------------------
// z draw + lpq/kl accumulation. One block per batch element (128 blocks).
// rq/rp: [B,128,256] with mean in ch 0:64, logvar in ch 64:128.
// ---------------------------------------------------------------------------
__global__ void zkl_kernel(const float* __restrict__ rq,
                           const float* __restrict__ rp,
                           const float* __restrict__ eps_t,
                           float* __restrict__ z,
                           float* __restrict__ klb,
                           float* __restrict__ lpqb) {
    const int b = blockIdx.x;
    const int tid = threadIdx.x;
    const float* rqb = rq + (size_t)b * 32768;
    const float* rpb = rp + (size_t)b * 32768;
    const float* eb  = eps_t + (size_t)b * 16384;
    float* zb = z + (size_t)b * 16384;

    float kl = 0.f, lpq = 0.f;
    for (int i = tid; i < 16384; i += 256) {
        float mq = rqb[i], lq = rqb[i + 16384];
        float mp = rpb[i], lp = rpb[i + 16384];
        float e  = eb[i];
        float zi = mq + expf(0.5f * lq) * e;
        zb[i] = zi;
        float dq = zi - mq, dp = zi - mp;
        lpq += 0.5f * ((lq + dq * dq * expf(-lq)) - (lp + dp * dp * expf(-lp)));
        float dm = mq - mp;
        kl  += 0.5f * (lp - lq + (expf(lq) + dm * dm) * expf(-lp) - 1.f);
    }
    __shared__ float s1[256], s2[256];
    s1[tid] = kl; s2[tid] = lpq;
    __syncthreads();
    for (int o = 128; o > 0; o >>= 1) {
        if (tid < o) { s1[tid] += s1[tid + o]; s2[tid] += s2[tid + o]; }
        __syncthreads();
    }
    if (tid == 0) { klb[b] += s1[0]; lpqb[b] += s2[0]; }
}

// ---------------------------------------------------------------------------
__global__ void copy_kernel(const float* __restrict__ src, float* __restrict__ dst, int n) {
    int i = blockIdx.x * blockDim.x + threadIdx.x;
    if (i < n) dst[i] = src[i];
}

__global__ void finalize_kernel(const float* __restrict__ klb,
                                const float* __restrict__ lpqb,
                                float* __restrict__ out_kl,
                                float* __restrict__ out_lpq) {
    __shared__ float s[128];
    int t = threadIdx.x;  // 128 threads
    s[t] = klb[t];
    out_lpq[t] = lpqb[t];
    __syncthreads();
    for (int o = 64; o > 0; o >>= 1) {
        if (t < o) s[t] += s[t + o];
        __syncthreads();
    }
    if (t == 0) out_kl[0] = s[0] / 128.f;
}

// ---------------------------------------------------------------------------
static void launch_conv(const Seg* segs, int nseg, const float* W, int cinTot,
                        const float* bias, const float* base, float* out, int cout) {
    ConvArgs a;
    for (int i = 0; i < 4; ++i) { a.seg[i].p = nullptr; a.seg[i].cin = 0; a.seg[i].cioff = 0; }
    for (int i = 0; i < nseg; ++i) a.seg[i] = segs[i];
    a.nseg = nseg; a.W = W; a.cinTot = cinTot;
    a.bias = bias; a.base = base; a.out = out; a.cout = cout;
    dim3 grid(cout / 32, BATCH);
    conv5x5_kernel<<<grid, 256>>>(a);
}

extern "C" void kernel_launch(void* const* d_in, const int* in_sizes, int n_in,
                              void* d_out, int out_size) {
    (void)in_sizes; (void)n_in; (void)out_size;
    const float* C_t    = (const float*)d_in[0];
    const float* D_t    = (const float*)d_in[1];
    const float* a_tmo  = (const float*)d_in[2];
    const float* s_tmo  = (const float*)d_in[3];
    const float* c_ssm_tmo = (const float*)d_in[4];
    const float* z_tmo  = (const float*)d_in[5];
    const float* eps    = (const float*)d_in[6];
    const float* W_ssm  = (const float*)d_in[7];
    const float* b_ssm  = (const float*)d_in[8];
    const float* W_p    = (const float*)d_in[9];
    const float* b_p    = (const float*)d_in[10];
    const float* W_q    = (const float*)d_in[11];
    const float* b_q    = (const float*)d_in[12];
    const float* W_rp   = (const float*)d_in[13];
    const float* b_rp   = (const float*)d_in[14];
    const float* W_rq   = (const float*)d_in[15];
    const float* b_rq   = (const float*)d_in[16];

    float* S;
    cudaGetSymbolAddress((void**)&S, g_scratch);
    float* static_q = S + OFF_STATIC_Q;
    float* static_p = S + OFF_STATIC_P;
    float* gates    = S + OFF_GATES;
    float* hp = S + OFF_HP;
    float* cp = S + OFF_CP;
    float* hq = S + OFF_HQ;
    float* cq = S + OFF_CQ;
    float* rq = S + OFF_RQ;
    float* rp = S + OFF_RP;
    float* zb = S + OFF_Z;
    float* klb  = S + OFF_KLB;
    float* lpqb = S + OFF_LPQB;

    float* out    = (float*)d_out;
    float* out_z  = out;                // 2097152
    float* out_s  = out + 2097152;      // 4194304
    float* out_c  = out + 6291456;      // 4194304
    float* out_kl = out + 10485760;
    float* out_lpq= out + 10485761;

    // zero state + accumulators
    cudaMemsetAsync(hp,  0, (size_t)4 * 4194304 * sizeof(float)); // hp,cp,hq,cq contiguous
    cudaMemsetAsync(klb, 0, 256 * sizeof(float));

    // ---- SSM ConvLSTM: input = [z_tmo(64), C_t(128), a_tmo(8), s_tmo(128)] ----
    {
        Seg segs[4] = { {z_tmo, 64, 0}, {C_t, 128, 64}, {a_tmo, 8, 192}, {s_tmo, 128, 200} };
        launch_conv(segs, 4, W_ssm, 328, b_ssm, nullptr, gates, 512);
        lstm_kernel<<<16384, 256>>>(gates, c_ssm_tmo, out_s, out_c);
    }

    // ---- static parts of q / p gates (loop-invariant) ----
    {
        // input_q = [hp(0:128), D_t(128:256), s_t(256:384), a_tmo(384:392), hq(392:520)]
        Seg segs[3] = { {D_t, 128, 128}, {out_s, 128, 256}, {a_tmo, 8, 384} };
        launch_conv(segs, 3, W_q, 520, b_q, nullptr, static_q, 512);
    }
    {
        // input_p = [z(0:64), C_t(64:192), s_t(192:320), a_tmo(320:328), hp(328:456)]
        Seg segs[3] = { {C_t, 128, 64}, {out_s, 128, 192}, {a_tmo, 8, 320} };
        launch_conv(segs, 3, W_p, 456, b_p, nullptr, static_p, 512);
    }

    for (int t = 0; t < STEPS; ++t) {
        // q-LSTM: dynamic channels hp, hq
        {
            Seg segs[2] = { {hp, 128, 0}, {hq, 128, 392} };
            launch_conv(segs, 2, W_q, 520, nullptr, static_q, gates, 512);
        }
        lstm_kernel<<<16384, 256>>>(gates, cq, hq, cq);

        // rq(hq), rp(hp)
        {
            Seg segs[1] = { {hq, 128, 0} };
            launch_conv(segs, 1, W_rq, 128, b_rq, nullptr, rq, 128);
        }
        {
            Seg segs[1] = { {hp, 128, 0} };
            launch_conv(segs, 1, W_rp, 128, b_rp, nullptr, rp, 128);
        }

        // z draw + kl/lpq accumulation
        zkl_kernel<<<128, 256>>>(rq, rp, eps + (size_t)t * 2097152, zb, klb, lpqb);

        // p-LSTM: dynamic channels z, hp
        {
            Seg segs[2] = { {zb, 64, 0}, {hp, 128, 328} };
            launch_conv(segs, 2, W_p, 456, nullptr, static_p, gates, 512);
        }
        lstm_kernel<<<16384, 256>>>(gates, cp, hp, cp);
    }

    // outputs
    copy_kernel<<<(2097152 + 255) / 256, 256>>>(zb, out_z, 2097152);
    finalize_kernel<<<1, 128>>>(klb, lpqb, out_kl, out_lpq);
}

// round 4
// speedup vs baseline: 2.4408x; 2.4408x over previous
#include <cuda_runtime.h>
#include <cstdint>
#include <math.h>

// ---------------------------------------------------------------------------
// TConvDRAW: B=128, NZ=64, NCL=NCC=NCS=128, NA=8, ZH=16, STEPS=6
// tf32 tensor-core conv (mma.sync m16n8k8), shifted-GEMM formulation.
// ---------------------------------------------------------------------------

#define PIX   256          // 16*16
#define BATCH 128
#define STEPS 6

// scratch offsets (in floats)
#define OFF_STATIC_Q 0u
#define OFF_STATIC_P 16777216u
#define OFF_GATES    33554432u
#define OFF_HP       50331648u
#define OFF_CP       54525952u
#define OFF_HQ       58720256u
#define OFF_CQ       62914560u
#define OFF_RQ       67108864u
#define OFF_RP       71303168u
#define OFF_Z        75497472u
#define OFF_KLB      77594624u
#define OFF_LPQB     77594752u
#define SCRATCH_N    77594880u

__device__ float g_scratch[SCRATCH_N];

// ---------------------------------------------------------------------------
struct Seg { const float* p; int cin; int cioff; };
struct ConvArgs {
    Seg seg[4];
    int nseg;
    const float* W;      // [cout, cinTot, 5, 5]
    int cinTot;
    const float* bias;   // [cout] or null
    const float* base;   // [B, cout, 256] or null
    float* out;          // [B, cout, 256]
    int cout;
};

__device__ __forceinline__ float to_tf32(float x) {
    uint32_t y;
    asm("cvt.rna.tf32.f32 %0, %1;" : "=r"(y) : "f"(x));
    return __uint_as_float(y);
}

__device__ __forceinline__ void mma_tf32(float& c0, float& c1, float& c2, float& c3,
                                         uint32_t a0, uint32_t a1, uint32_t a2, uint32_t a3,
                                         uint32_t b0, uint32_t b1) {
    asm volatile(
        "mma.sync.aligned.m16n8k8.row.col.f32.tf32.tf32.f32 "
        "{%0,%1,%2,%3}, {%4,%5,%6,%7}, {%8,%9}, {%0,%1,%2,%3};"
        : "+f"(c0), "+f"(c1), "+f"(c2), "+f"(c3)
        : "r"(a0), "r"(a1), "r"(a2), "r"(a3), "r"(b0), "r"(b1));
}

// Plane smem: 8 ci, each padded 20 rows x 24 cols, per-ci stride 488 (bank-safe)
#define PLANE_CI_STRIDE 488
#define PLANE_FLOATS    (8 * PLANE_CI_STRIDE)          // 3904
// Weight smem: sw[tap][ci][co], ci stride 72 (bank-safe), tap stride 576
#define SW_CI_STRIDE 72
#define SW_TAP_STRIDE 576
#define SW_FLOATS (25 * SW_TAP_STRIDE)                  // 14400
#define CONV_SMEM_BYTES ((PLANE_FLOATS + SW_FLOATS) * 4)  // 73216

// Block: 256 threads = 8 warps (2 M-warps x 4 N-warps).
// Tile: 64 couts x 256 pixels x 1 image. grid = (cout/64, BATCH)
__global__ void __launch_bounds__(256, 2) conv5x5_mma_kernel(ConvArgs a) {
    extern __shared__ float smem[];
    float* plane = smem;                 // PLANE_FLOATS
    float* sw    = smem + PLANE_FLOATS;  // SW_FLOATS

    const int b      = blockIdx.y;
    const int coBase = blockIdx.x * 64;
    const int tid    = threadIdx.x;
    const int lane   = tid & 31;
    const int warp   = tid >> 5;
    const int wm     = warp & 1;    // 0..1  (co  32 each)
    const int wn     = warp >> 1;   // 0..3  (pix 64 each)
    const int tig    = lane & 3;    // threadID_in_group
    const int g      = lane >> 2;   // groupID

    // per-thread fragment base addresses (floats)
    const int aBase = tig * SW_CI_STRIDE + wm * 32 + g;
    int bBase[8];
#pragma unroll
    for (int n = 0; n < 8; ++n) {
        int p  = wn * 64 + n * 8;       // pixel base of this n-tile
        int rn = p >> 4, cn = p & 15;
        bBase[n] = tig * PLANE_CI_STRIDE + rn * 24 + cn + g;
    }

    float acc[2][8][4];
#pragma unroll
    for (int m = 0; m < 2; ++m)
#pragma unroll
        for (int n = 0; n < 8; ++n)
#pragma unroll
            for (int k = 0; k < 4; ++k) acc[m][n][k] = 0.f;

    for (int s = 0; s < a.nseg; ++s) {
        const float* src  = a.seg[s].p + (size_t)b * a.seg[s].cin * PIX;
        const int    cin  = a.seg[s].cin;
        const int    coff = a.seg[s].cioff;
        for (int ci0 = 0; ci0 < cin; ci0 += 8) {
            __syncthreads();
            // ---- stage 8 input planes (padded, zero halo, tf32-rounded) ----
            for (int i = tid; i < 8 * 480; i += 256) {
                int ci = i / 480;
                int j  = i % 480;
                int r  = j / 24, c = j % 24;
                float v = 0.f;
                if ((unsigned)(r - 2) < 16u && (unsigned)(c - 2) < 16u)
                    v = src[(ci0 + ci) * PIX + (r - 2) * 16 + (c - 2)];
                plane[ci * PLANE_CI_STRIDE + r * 24 + c] = to_tf32(v);
            }
            // ---- stage weights: 64 co x 8 ci x 25 taps ----
            for (int i = tid; i < 64 * 8 * 25; i += 256) {
                int tap = i % 25;
                int ci  = (i / 25) & 7;
                int co  = i / 200;
                float w = a.W[((size_t)(coBase + co) * a.cinTot + coff + ci0 + ci) * 25 + tap];
                sw[tap * SW_TAP_STRIDE + ci * SW_CI_STRIDE + co] = to_tf32(w);
            }
            __syncthreads();

            // ---- 25 taps x (8 ci K-slice) of MMAs ----
            for (int dy = 0; dy < 5; ++dy) {
#pragma unroll
                for (int dx = 0; dx < 5; ++dx) {
                    const int tap = dy * 5 + dx;
                    const float* A0 = sw + tap * SW_TAP_STRIDE + aBase;
                    uint32_t afr[2][4];
#pragma unroll
                    for (int m = 0; m < 2; ++m) {
                        afr[m][0] = __float_as_uint(A0[m * 16]);
                        afr[m][1] = __float_as_uint(A0[m * 16 + 8]);
                        afr[m][2] = __float_as_uint(A0[m * 16 + 4 * SW_CI_STRIDE]);
                        afr[m][3] = __float_as_uint(A0[m * 16 + 4 * SW_CI_STRIDE + 8]);
                    }
                    const int boff = dy * 24 + dx;
#pragma unroll
                    for (int n = 0; n < 8; ++n) {
                        const float* Bp = plane + bBase[n] + boff;
                        uint32_t b0 = __float_as_uint(Bp[0]);
                        uint32_t b1 = __float_as_uint(Bp[4 * PLANE_CI_STRIDE]);
#pragma unroll
                        for (int m = 0; m < 2; ++m)
                            mma_tf32(acc[m][n][0], acc[m][n][1], acc[m][n][2], acc[m][n][3],
                                     afr[m][0], afr[m][1], afr[m][2], afr[m][3], b0, b1);
                    }
                }
            }
        }
    }

    // ---- epilogue ----
#pragma unroll
    for (int m = 0; m < 2; ++m) {
        const int row0 = coBase + wm * 32 + m * 16 + g;
        const int row1 = row0 + 8;
        const float bias0 = a.bias ? a.bias[row0] : 0.f;
        const float bias1 = a.bias ? a.bias[row1] : 0.f;
#pragma unroll
        for (int n = 0; n < 8; ++n) {
            const int col = wn * 64 + n * 8 + 2 * tig;
            size_t o0 = ((size_t)b * a.cout + row0) * PIX + col;
            size_t o1 = ((size_t)b * a.cout + row1) * PIX + col;
            float v0 = acc[m][n][0] + bias0;
            float v1 = acc[m][n][1] + bias0;
            float v2 = acc[m][n][2] + bias1;
            float v3 = acc[m][n][3] + bias1;
            if (a.base) {
                v0 += a.base[o0];     v1 += a.base[o0 + 1];
                v2 += a.base[o1];     v3 += a.base[o1 + 1];
            }
            a.out[o0]     = v0;
            a.out[o0 + 1] = v1;
            a.out[o1]     = v2;
            a.out[o1 + 1] = v3;
        }
    }
}

// ---------------------------------------------------------------------------
__device__ __forceinline__ float sigmoidf_(float x) { return 1.f / (1.f + expf(-x)); }

__global__ void lstm_kernel(const float* __restrict__ gates,
                            const float* __restrict__ c_in,
                            float* __restrict__ h_out,
                            float* __restrict__ c_out) {
    int idx = blockIdx.x * blockDim.x + threadIdx.x;
    if (idx >= 4194304) return;
    int b = idx >> 15;
    int r = idx & 32767;
    size_t g0 = (size_t)b * 131072 + r;
    float ig = gates[g0];
    float fg = gates[g0 + 32768];
    float og = gates[g0 + 65536];
    float gg = gates[g0 + 98304];
    float c  = sigmoidf_(fg) * c_in[idx] + sigmoidf_(ig) * tanhf(gg);
    c_out[idx] = c;
    h_out[idx] = sigmoidf_(og) * tanhf(c);
}

// ---------------------------------------------------------------------------
__global__ void zkl_kernel(const float* __restrict__ rq,
                           const float* __restrict__ rp,
                           const float* __restrict__ eps_t,
                           float* __restrict__ z,
                           float* __restrict__ klb,
                           float* __restrict__ lpqb) {
    const int b = blockIdx.x;
    const int tid = threadIdx.x;
    const float* rqb = rq + (size_t)b * 32768;
    const float* rpb = rp + (size_t)b * 32768;
    const float* eb  = eps_t + (size_t)b * 16384;
    float* zb = z + (size_t)b * 16384;

    float kl = 0.f, lpq = 0.f;
    for (int i = tid; i < 16384; i += 256) {
        float mq = rqb[i], lq = rqb[i + 16384];
        float mp = rpb[i], lp = rpb[i + 16384];
        float e  = eb[i];
        float zi = mq + expf(0.5f * lq) * e;
        zb[i] = zi;
        float dq = zi - mq, dp = zi - mp;
        lpq += 0.5f * ((lq + dq * dq * expf(-lq)) - (lp + dp * dp * expf(-lp)));
        float dm = mq - mp;
        kl  += 0.5f * (lp - lq + (expf(lq) + dm * dm) * expf(-lp) - 1.f);
    }
    __shared__ float s1[256], s2[256];
    s1[tid] = kl; s2[tid] = lpq;
    __syncthreads();
    for (int o = 128; o > 0; o >>= 1) {
        if (tid < o) { s1[tid] += s1[tid + o]; s2[tid] += s2[tid + o]; }
        __syncthreads();
    }
    if (tid == 0) { klb[b] += s1[0]; lpqb[b] += s2[0]; }
}

// ---------------------------------------------------------------------------
__global__ void copy_kernel(const float* __restrict__ src, float* __restrict__ dst, int n) {
    int i = blockIdx.x * blockDim.x + threadIdx.x;
    if (i < n) dst[i] = src[i];
}

__global__ void finalize_kernel(const float* __restrict__ klb,
                                const float* __restrict__ lpqb,
                                float* __restrict__ out_kl,
                                float* __restrict__ out_lpq) {
    __shared__ float s[128];
    int t = threadIdx.x;
    s[t] = klb[t];
    out_lpq[t] = lpqb[t];
    __syncthreads();
    for (int o = 64; o > 0; o >>= 1) {
        if (t < o) s[t] += s[t + o];
        __syncthreads();
    }
    if (t == 0) out_kl[0] = s[0] / 128.f;
}

// ---------------------------------------------------------------------------
static void launch_conv(const Seg* segs, int nseg, const float* W, int cinTot,
                        const float* bias, const float* base, float* out, int cout) {
    ConvArgs a;
    for (int i = 0; i < 4; ++i) { a.seg[i].p = nullptr; a.seg[i].cin = 0; a.seg[i].cioff = 0; }
    for (int i = 0; i < nseg; ++i) a.seg[i] = segs[i];
    a.nseg = nseg; a.W = W; a.cinTot = cinTot;
    a.bias = bias; a.base = base; a.out = out; a.cout = cout;
    dim3 grid(cout / 64, BATCH);
    conv5x5_mma_kernel<<<grid, 256, CONV_SMEM_BYTES>>>(a);
}

extern "C" void kernel_launch(void* const* d_in, const int* in_sizes, int n_in,
                              void* d_out, int out_size) {
    (void)in_sizes; (void)n_in; (void)out_size;
    const float* C_t    = (const float*)d_in[0];
    const float* D_t    = (const float*)d_in[1];
    const float* a_tmo  = (const float*)d_in[2];
    const float* s_tmo  = (const float*)d_in[3];
    const float* c_ssm_tmo = (const float*)d_in[4];
    const float* z_tmo  = (const float*)d_in[5];
    const float* eps    = (const float*)d_in[6];
    const float* W_ssm  = (const float*)d_in[7];
    const float* b_ssm  = (const float*)d_in[8];
    const float* W_p    = (const float*)d_in[9];
    const float* b_p    = (const float*)d_in[10];
    const float* W_q    = (const float*)d_in[11];
    const float* b_q    = (const float*)d_in[12];
    const float* W_rp   = (const float*)d_in[13];
    const float* b_rp   = (const float*)d_in[14];
    const float* W_rq   = (const float*)d_in[15];
    const float* b_rq   = (const float*)d_in[16];

    static int smem_set = -1;
    if (smem_set < 0) {
        cudaFuncSetAttribute(conv5x5_mma_kernel,
                             cudaFuncAttributeMaxDynamicSharedMemorySize, CONV_SMEM_BYTES);
        smem_set = 1;
    }

    float* S;
    cudaGetSymbolAddress((void**)&S, g_scratch);
    float* static_q = S + OFF_STATIC_Q;
    float* static_p = S + OFF_STATIC_P;
    float* gates    = S + OFF_GATES;
    float* hp = S + OFF_HP;
    float* cp = S + OFF_CP;
    float* hq = S + OFF_HQ;
    float* cq = S + OFF_CQ;
    float* rq = S + OFF_RQ;
    float* rp = S + OFF_RP;
    float* zb = S + OFF_Z;
    float* klb  = S + OFF_KLB;
    float* lpqb = S + OFF_LPQB;

    float* out    = (float*)d_out;
    float* out_z  = out;
    float* out_s  = out + 2097152;
    float* out_c  = out + 6291456;
    float* out_kl = out + 10485760;
    float* out_lpq= out + 10485761;

    cudaMemsetAsync(hp,  0, (size_t)4 * 4194304 * sizeof(float));
    cudaMemsetAsync(klb, 0, 256 * sizeof(float));

    // ---- SSM ConvLSTM: input = [z_tmo(64), C_t(128), a_tmo(8), s_tmo(128)] ----
    {
        Seg segs[4] = { {z_tmo, 64, 0}, {C_t, 128, 64}, {a_tmo, 8, 192}, {s_tmo, 128, 200} };
        launch_conv(segs, 4, W_ssm, 328, b_ssm, nullptr, gates, 512);
        lstm_kernel<<<16384, 256>>>(gates, c_ssm_tmo, out_s, out_c);
    }

    // ---- static parts of q / p gates (loop-invariant) ----
    {
        Seg segs[3] = { {D_t, 128, 128}, {out_s, 128, 256}, {a_tmo, 8, 384} };
        launch_conv(segs, 3, W_q, 520, b_q, nullptr, static_q, 512);
    }
    {
        Seg segs[3] = { {C_t, 128, 64}, {out_s, 128, 192}, {a_tmo, 8, 320} };
        launch_conv(segs, 3, W_p, 456, b_p, nullptr, static_p, 512);
    }

    for (int t = 0; t < STEPS; ++t) {
        {
            Seg segs[2] = { {hp, 128, 0}, {hq, 128, 392} };
            launch_conv(segs, 2, W_q, 520, nullptr, static_q, gates, 512);
        }
        lstm_kernel<<<16384, 256>>>(gates, cq, hq, cq);

        {
            Seg segs[1] = { {hq, 128, 0} };
            launch_conv(segs, 1, W_rq, 128, b_rq, nullptr, rq, 128);
        }
        {
            Seg segs[1] = { {hp, 128, 0} };
            launch_conv(segs, 1, W_rp, 128, b_rp, nullptr, rp, 128);
        }

        zkl_kernel<<<128, 256>>>(rq, rp, eps + (size_t)t * 2097152, zb, klb, lpqb);

        {
            Seg segs[2] = { {zb, 64, 0}, {hp, 128, 328} };
            launch_conv(segs, 2, W_p, 456, nullptr, static_p, gates, 512);
        }
        lstm_kernel<<<16384, 256>>>(gates, cp, hp, cp);
    }

    copy_kernel<<<(2097152 + 255) / 256, 256>>>(zb, out_z, 2097152);
    finalize_kernel<<<1, 128>>>(klb, lpqb, out_kl, out_lpq);
}

// round 5
// speedup vs baseline: 3.8747x; 1.5875x over previous
#include <cuda_runtime.h>
#include <cstdint>
#include <math.h>

// ---------------------------------------------------------------------------
// TConvDRAW: B=128, NZ=64, NCL=NCC=NCS=128, NA=8, ZH=16, STEPS=6
// tf32 mma.sync conv, shifted-GEMM, packed-fragment smem layouts.
// ---------------------------------------------------------------------------

#define PIX   256
#define BATCH 128
#define STEPS 6

// scratch offsets (in floats)
#define OFF_STATIC_Q 0u
#define OFF_STATIC_P 16777216u
#define OFF_GATES    33554432u
#define OFF_HP       50331648u
#define OFF_CP       54525952u
#define OFF_HQ       58720256u
#define OFF_CQ       62914560u
#define OFF_RQ       67108864u
#define OFF_RP       71303168u
#define OFF_Z        75497472u
#define OFF_KLB      77594624u
#define OFF_LPQB     77594752u
// packed tf32 weights
#define OFF_PW_SSM   77594880u                       // 8*41*12800  = 4198400
#define OFF_PW_Q     (OFF_PW_SSM + 4198400u)         // 8*65*12800  = 6656000
#define OFF_PW_P     (OFF_PW_Q   + 6656000u)         // 8*57*12800  = 5836800
#define OFF_PW_RQ    (OFF_PW_P   + 5836800u)         // 2*16*12800  = 409600
#define OFF_PW_RP    (OFF_PW_RQ  + 409600u)
#define SCRATCH_N    (OFF_PW_RP  + 409600u)

__device__ float g_scratch[SCRATCH_N];

__device__ __forceinline__ float to_tf32(float x) {
    uint32_t y;
    asm("cvt.rna.tf32.f32 %0, %1;" : "=r"(y) : "f"(x));
    return __uint_as_float(y);
}

__device__ __forceinline__ void mma_tf32(float& c0, float& c1, float& c2, float& c3,
                                         float a0, float a1, float a2, float a3,
                                         float b0, float b1) {
    asm volatile(
        "mma.sync.aligned.m16n8k8.row.col.f32.tf32.tf32.f32 "
        "{%0,%1,%2,%3}, {%4,%5,%6,%7}, {%8,%9}, {%0,%1,%2,%3};"
        : "+f"(c0), "+f"(c1), "+f"(c2), "+f"(c3)
        : "r"(__float_as_uint(a0)), "r"(__float_as_uint(a1)),
          "r"(__float_as_uint(a2)), "r"(__float_as_uint(a3)),
          "r"(__float_as_uint(b0)), "r"(__float_as_uint(b1)));
}

// ---------------------------------------------------------------------------
// Weight repack: W[cout, cinTot, 5, 5] -> PW[cg][chunk][tap][pack][lane][slot]
// (12800 floats per (cg,chunk)), tf32-rounded.
// ---------------------------------------------------------------------------
__global__ void repack_kernel(const float* __restrict__ W, float* __restrict__ PW,
                              int cinTot, int nChunks, int total) {
    int idx = blockIdx.x * 256 + threadIdx.x;
    if (idx >= total) return;
    int d       = idx % 12800;
    int cgchunk = idx / 12800;
    int chunk   = cgchunk % nChunks;
    int cg      = cgchunk / nChunks;
    int slot = d & 3;
    int lane = (d >> 2) & 31;
    int pack = (d >> 7) & 3;
    int tap  = d >> 9;
    int co = cg * 64 + (pack >> 1) * 32 + (pack & 1) * 16 + ((slot & 1) << 3) + (lane >> 2);
    int ci = chunk * 8 + (lane & 3) + ((slot >> 1) << 2);
    PW[idx] = to_tf32(W[((size_t)co * cinTot + ci) * 25 + tap]);
}

// ---------------------------------------------------------------------------
struct Seg { const float* p; int cin; int chunkBase; };
struct ConvArgs {
    Seg seg[4];
    int nseg;
    const float* PW;     // packed weights
    int nChunks;         // cinTot/8
    const float* bias;   // [cout] or null
    const float* base;   // [B, cout, 256] or null
    float* out;          // [B, cout, 256]
    int cout;
};

// plane: [20 rows][32 cols][8 k-slots] = 5120 floats
// sw:    [25 taps][4 packs][32 lanes][4 slots] = 12800 floats
#define PLANE_FLOATS 5120
#define SW_FLOATS    12800
#define CONV_SMEM_BYTES ((PLANE_FLOATS + SW_FLOATS) * 4)   // 71680

__global__ void __launch_bounds__(256, 2) conv5x5_mma_kernel(ConvArgs a) {
    extern __shared__ float smem[];
    float* plane = smem;
    float* sw    = smem + PLANE_FLOATS;

    const int b    = blockIdx.y;
    const int cg   = blockIdx.x;
    const int tid  = threadIdx.x;
    const int lane = tid & 31;
    const int warp = tid >> 5;
    const int wm   = warp & 1;
    const int wn   = warp >> 1;
    const int tig  = lane & 3;
    const int g    = lane >> 2;

    int bBase[8];
#pragma unroll
    for (int n = 0; n < 8; ++n) {
        int p  = wn * 64 + n * 8;
        int rn = p >> 4, cn = p & 15;
        bBase[n] = (rn * 32 + cn + g) * 8 + 2 * tig;
    }

    float acc[2][8][4];
#pragma unroll
    for (int m = 0; m < 2; ++m)
#pragma unroll
        for (int n = 0; n < 8; ++n)
#pragma unroll
            for (int k = 0; k < 4; ++k) acc[m][n][k] = 0.f;

    for (int s = 0; s < a.nseg; ++s) {
        const float* src = a.seg[s].p + (size_t)b * a.seg[s].cin * PIX;
        const int nchk   = a.seg[s].cin >> 3;
        for (int c8 = 0; c8 < nchk; ++c8) {
            const int chunk = a.seg[s].chunkBase + c8;
            __syncthreads();
            // ---- stage packed weights (coalesced LDG.128 -> STS.128) ----
            {
                const float4* pw = (const float4*)(a.PW + (size_t)(cg * a.nChunks + chunk) * 12800);
                float4* swv = (float4*)sw;
                for (int j = tid; j < 3200; j += 256) swv[j] = pw[j];
            }
            // ---- stage 8 input planes, k-interleaved layout ----
#pragma unroll
            for (int k = 0; k < 8; ++k) {
                const int slotk = 2 * (k & 3) + (k >> 2);
                const float* sk = src + (c8 * 8 + k) * PIX;
                for (int pp = tid; pp < 640; pp += 256) {
                    int row = pp >> 5, col = pp & 31;
                    float v = 0.f;
                    if ((unsigned)(row - 2) < 16u && (unsigned)(col - 2) < 16u)
                        v = sk[(row - 2) * 16 + (col - 2)];
                    plane[pp * 8 + slotk] = to_tf32(v);
                }
            }
            __syncthreads();

            // ---- 25 taps x k8 MMAs ----
#pragma unroll
            for (int dy = 0; dy < 5; ++dy) {
#pragma unroll
                for (int dx = 0; dx < 5; ++dx) {
                    const int tap = dy * 5 + dx;
                    const float4* A = (const float4*)sw + (tap * 4 + wm * 2) * 32 + lane;
                    const float4 a0 = A[0];
                    const float4 a1 = A[32];
                    const int boff = (dy * 32 + dx) * 8;
#pragma unroll
                    for (int n = 0; n < 8; ++n) {
                        const float2 bv = *(const float2*)(plane + bBase[n] + boff);
                        mma_tf32(acc[0][n][0], acc[0][n][1], acc[0][n][2], acc[0][n][3],
                                 a0.x, a0.y, a0.z, a0.w, bv.x, bv.y);
                        mma_tf32(acc[1][n][0], acc[1][n][1], acc[1][n][2], acc[1][n][3],
                                 a1.x, a1.y, a1.z, a1.w, bv.x, bv.y);
                    }
                }
            }
        }
    }

    // ---- epilogue ----
    const int coBase = cg * 64;
#pragma unroll
    for (int m = 0; m < 2; ++m) {
        const int row0 = coBase + wm * 32 + m * 16 + g;
        const int row1 = row0 + 8;
        const float bias0 = a.bias ? a.bias[row0] : 0.f;
        const float bias1 = a.bias ? a.bias[row1] : 0.f;
#pragma unroll
        for (int n = 0; n < 8; ++n) {
            const int col = wn * 64 + n * 8 + 2 * tig;
            size_t o0 = ((size_t)b * a.cout + row0) * PIX + col;
            size_t o1 = ((size_t)b * a.cout + row1) * PIX + col;
            float v0 = acc[m][n][0] + bias0;
            float v1 = acc[m][n][1] + bias0;
            float v2 = acc[m][n][2] + bias1;
            float v3 = acc[m][n][3] + bias1;
            if (a.base) {
                v0 += a.base[o0];     v1 += a.base[o0 + 1];
                v2 += a.base[o1];     v3 += a.base[o1 + 1];
            }
            a.out[o0]     = v0;
            a.out[o0 + 1] = v1;
            a.out[o1]     = v2;
            a.out[o1 + 1] = v3;
        }
    }
}

// ---------------------------------------------------------------------------
__device__ __forceinline__ float sigmoidf_(float x) { return 1.f / (1.f + expf(-x)); }

__global__ void lstm_kernel(const float* __restrict__ gates,
                            const float* __restrict__ c_in,
                            float* __restrict__ h_out,
                            float* __restrict__ c_out) {
    int idx = blockIdx.x * blockDim.x + threadIdx.x;
    if (idx >= 4194304) return;
    int b = idx >> 15;
    int r = idx & 32767;
    size_t g0 = (size_t)b * 131072 + r;
    float ig = gates[g0];
    float fg = gates[g0 + 32768];
    float og = gates[g0 + 65536];
    float gg = gates[g0 + 98304];
    float c  = sigmoidf_(fg) * c_in[idx] + sigmoidf_(ig) * tanhf(gg);
    c_out[idx] = c;
    h_out[idx] = sigmoidf_(og) * tanhf(c);
}

// ---------------------------------------------------------------------------
__global__ void zkl_kernel(const float* __restrict__ rq,
                           const float* __restrict__ rp,
                           const float* __restrict__ eps_t,
                           float* __restrict__ z,
                           float* __restrict__ klb,
                           float* __restrict__ lpqb) {
    const int b = blockIdx.x;
    const int tid = threadIdx.x;
    const float* rqb = rq + (size_t)b * 32768;
    const float* rpb = rp + (size_t)b * 32768;
    const float* eb  = eps_t + (size_t)b * 16384;
    float* zb = z + (size_t)b * 16384;

    float kl = 0.f, lpq = 0.f;
    for (int i = tid; i < 16384; i += 256) {
        float mq = rqb[i], lq = rqb[i + 16384];
        float mp = rpb[i], lp = rpb[i + 16384];
        float e  = eb[i];
        float zi = mq + expf(0.5f * lq) * e;
        zb[i] = zi;
        float dq = zi - mq, dp = zi - mp;
        lpq += 0.5f * ((lq + dq * dq * expf(-lq)) - (lp + dp * dp * expf(-lp)));
        float dm = mq - mp;
        kl  += 0.5f * (lp - lq + (expf(lq) + dm * dm) * expf(-lp) - 1.f);
    }
    __shared__ float s1[256], s2[256];
    s1[tid] = kl; s2[tid] = lpq;
    __syncthreads();
    for (int o = 128; o > 0; o >>= 1) {
        if (tid < o) { s1[tid] += s1[tid + o]; s2[tid] += s2[tid + o]; }
        __syncthreads();
    }
    if (tid == 0) { klb[b] += s1[0]; lpqb[b] += s2[0]; }
}

// ---------------------------------------------------------------------------
__global__ void copy_kernel(const float* __restrict__ src, float* __restrict__ dst, int n) {
    int i = blockIdx.x * blockDim.x + threadIdx.x;
    if (i < n) dst[i] = src[i];
}

__global__ void finalize_kernel(const float* __restrict__ klb,
                                const float* __restrict__ lpqb,
                                float* __restrict__ out_kl,
                                float* __restrict__ out_lpq) {
    __shared__ float s[128];
    int t = threadIdx.x;
    s[t] = klb[t];
    out_lpq[t] = lpqb[t];
    __syncthreads();
    for (int o = 64; o > 0; o >>= 1) {
        if (t < o) s[t] += s[t + o];
        __syncthreads();
    }
    if (t == 0) out_kl[0] = s[0] / 128.f;
}

// ---------------------------------------------------------------------------
static void launch_conv(const Seg* segs, int nseg, const float* PW, int nChunks,
                        const float* bias, const float* base, float* out, int cout) {
    ConvArgs a;
    for (int i = 0; i < 4; ++i) { a.seg[i].p = nullptr; a.seg[i].cin = 0; a.seg[i].chunkBase = 0; }
    for (int i = 0; i < nseg; ++i) a.seg[i] = segs[i];
    a.nseg = nseg; a.PW = PW; a.nChunks = nChunks;
    a.bias = bias; a.base = base; a.out = out; a.cout = cout;
    dim3 grid(cout / 64, BATCH);
    conv5x5_mma_kernel<<<grid, 256, CONV_SMEM_BYTES>>>(a);
}

static void launch_repack(const float* W, float* PW, int cinTot, int cout) {
    int nChunks = cinTot / 8;
    int total = (cout / 64) * nChunks * 12800;
    repack_kernel<<<(total + 255) / 256, 256>>>(W, PW, cinTot, nChunks, total);
}

extern "C" void kernel_launch(void* const* d_in, const int* in_sizes, int n_in,
                              void* d_out, int out_size) {
    (void)in_sizes; (void)n_in; (void)out_size;
    const float* C_t    = (const float*)d_in[0];
    const float* D_t    = (const float*)d_in[1];
    const float* a_tmo  = (const float*)d_in[2];
    const float* s_tmo  = (const float*)d_in[3];
    const float* c_ssm_tmo = (const float*)d_in[4];
    const float* z_tmo  = (const float*)d_in[5];
    const float* eps    = (const float*)d_in[6];
    const float* W_ssm  = (const float*)d_in[7];
    const float* b_ssm  = (const float*)d_in[8];
    const float* W_p    = (const float*)d_in[9];
    const float* b_p    = (const float*)d_in[10];
    const float* W_q    = (const float*)d_in[11];
    const float* b_q    = (const float*)d_in[12];
    const float* W_rp   = (const float*)d_in[13];
    const float* b_rp   = (const float*)d_in[14];
    const float* W_rq   = (const float*)d_in[15];
    const float* b_rq   = (const float*)d_in[16];

    static int smem_set = -1;
    if (smem_set < 0) {
        cudaFuncSetAttribute(conv5x5_mma_kernel,
                             cudaFuncAttributeMaxDynamicSharedMemorySize, CONV_SMEM_BYTES);
        smem_set = 1;
    }

    float* S;
    cudaGetSymbolAddress((void**)&S, g_scratch);
    float* static_q = S + OFF_STATIC_Q;
    float* static_p = S + OFF_STATIC_P;
    float* gates    = S + OFF_GATES;
    float* hp = S + OFF_HP;
    float* cp = S + OFF_CP;
    float* hq = S + OFF_HQ;
    float* cq = S + OFF_CQ;
    float* rq = S + OFF_RQ;
    float* rp = S + OFF_RP;
    float* zb = S + OFF_Z;
    float* klb  = S + OFF_KLB;
    float* lpqb = S + OFF_LPQB;
    float* pw_ssm = S + OFF_PW_SSM;
    float* pw_q   = S + OFF_PW_Q;
    float* pw_p   = S + OFF_PW_P;
    float* pw_rq  = S + OFF_PW_RQ;
    float* pw_rp  = S + OFF_PW_RP;

    float* out    = (float*)d_out;
    float* out_z  = out;
    float* out_s  = out + 2097152;
    float* out_c  = out + 6291456;
    float* out_kl = out + 10485760;
    float* out_lpq= out + 10485761;

    cudaMemsetAsync(hp,  0, (size_t)4 * 4194304 * sizeof(float));
    cudaMemsetAsync(klb, 0, 256 * sizeof(float));

    // ---- repack + tf32-convert all weights ----
    launch_repack(W_ssm, pw_ssm, 328, 512);
    launch_repack(W_q,   pw_q,   520, 512);
    launch_repack(W_p,   pw_p,   456, 512);
    launch_repack(W_rq,  pw_rq,  128, 128);
    launch_repack(W_rp,  pw_rp,  128, 128);

    // ---- SSM ConvLSTM: [z_tmo(0), C_t(64), a_tmo(192), s_tmo(200)] / 328 ----
    {
        Seg segs[4] = { {z_tmo, 64, 0}, {C_t, 128, 8}, {a_tmo, 8, 24}, {s_tmo, 128, 25} };
        launch_conv(segs, 4, pw_ssm, 41, b_ssm, nullptr, gates, 512);
        lstm_kernel<<<16384, 256>>>(gates, c_ssm_tmo, out_s, out_c);
    }

    // ---- static parts of q / p gates ----
    {
        // q input: [hp 0, D_t 128, s_t 256, a_tmo 384, hq 392] / 520
        Seg segs[3] = { {D_t, 128, 16}, {out_s, 128, 32}, {a_tmo, 8, 48} };
        launch_conv(segs, 3, pw_q, 65, b_q, nullptr, static_q, 512);
    }
    {
        // p input: [z 0, C_t 64, s_t 192, a_tmo 320, hp 328] / 456
        Seg segs[3] = { {C_t, 128, 8}, {out_s, 128, 24}, {a_tmo, 8, 40} };
        launch_conv(segs, 3, pw_p, 57, b_p, nullptr, static_p, 512);
    }

    for (int t = 0; t < STEPS; ++t) {
        {
            Seg segs[2] = { {hp, 128, 0}, {hq, 128, 49} };
            launch_conv(segs, 2, pw_q, 65, nullptr, static_q, gates, 512);
        }
        lstm_kernel<<<16384, 256>>>(gates, cq, hq, cq);

        {
            Seg segs[1] = { {hq, 128, 0} };
            launch_conv(segs, 1, pw_rq, 16, b_rq, nullptr, rq, 128);
        }
        {
            Seg segs[1] = { {hp, 128, 0} };
            launch_conv(segs, 1, pw_rp, 16, b_rp, nullptr, rp, 128);
        }

        zkl_kernel<<<128, 256>>>(rq, rp, eps + (size_t)t * 2097152, zb, klb, lpqb);

        {
            Seg segs[2] = { {zb, 64, 0}, {hp, 128, 41} };
            launch_conv(segs, 2, pw_p, 57, nullptr, static_p, gates, 512);
        }
        lstm_kernel<<<16384, 256>>>(gates, cp, hp, cp);
    }

    copy_kernel<<<(2097152 + 255) / 256, 256>>>(zb, out_z, 2097152);
    finalize_kernel<<<1, 128>>>(klb, lpqb, out_kl, out_lpq);
}

// round 7
// speedup vs baseline: 5.9700x; 1.5408x over previous
#include <cuda_runtime.h>
#include <cstdint>
#include <math.h>

// ---------------------------------------------------------------------------
// TConvDRAW: B=128, NZ=64, NCL=NCC=NCS=128, NA=8, ZH=16, STEPS=6
// tf32 mma.sync conv, cp.async double-buffered pipeline, producer-side
// tf32 rounding + padding.
// ---------------------------------------------------------------------------

#define PIX   256
#define BATCH 128
#define STEPS 6

// scratch offsets (floats)
#define OFF_STATIC_Q 0u
#define OFF_STATIC_P 16777216u
#define OFF_GATES    33554432u
#define OFF_CP       50331648u
#define OFF_CQ       54525952u
#define OFF_RQ       58720256u
#define OFF_RP       62914560u
#define OFF_Z        67108864u
#define OFF_KLB      69206016u
#define OFF_LPQB     69206144u
#define OFF_PW_SSM   69206272u
#define OFF_PW_Q     73404672u
#define OFF_PW_P     80060672u
#define OFF_PW_RQ    85897472u
#define OFF_PW_RP    86307072u
#define OFF_PAD_C    86716672u
#define OFF_PAD_D    97202432u
#define OFF_PAD_A    107688192u
#define OFF_PAD_STMO 108343552u
#define OFF_PAD_ZTMO 118829312u
#define OFF_PAD_ST   124072192u
#define OFF_PAD_HP   134557952u
#define OFF_PAD_HQ   145043712u
#define OFF_PAD_ZB   155529472u
#define SCRATCH_N    160772352u

// pad_st + pad_hp + pad_hq + pad_zb, in floats (3*10485760 + 5242880)
#define PAD_STATE_FLOATS 36700160u

__device__ float g_scratch[SCRATCH_N];

__device__ __forceinline__ float to_tf32(float x) {
    uint32_t y;
    asm("cvt.rna.tf32.f32 %0, %1;" : "=r"(y) : "f"(x));
    return __uint_as_float(y);
}

__device__ __forceinline__ void mma_tf32(float& c0, float& c1, float& c2, float& c3,
                                         float a0, float a1, float a2, float a3,
                                         float b0, float b1) {
    asm volatile(
        "mma.sync.aligned.m16n8k8.row.col.f32.tf32.tf32.f32 "
        "{%0,%1,%2,%3}, {%4,%5,%6,%7}, {%8,%9}, {%0,%1,%2,%3};"
        : "+f"(c0), "+f"(c1), "+f"(c2), "+f"(c3)
        : "r"(__float_as_uint(a0)), "r"(__float_as_uint(a1)),
          "r"(__float_as_uint(a2)), "r"(__float_as_uint(a3)),
          "r"(__float_as_uint(b0)), "r"(__float_as_uint(b1)));
}

__device__ __forceinline__ void cpasync16(uint32_t s, const void* g) {
    asm volatile("cp.async.cg.shared.global [%0], [%1], 16;" :: "r"(s), "l"(g));
}
__device__ __forceinline__ void cpcommit() {
    asm volatile("cp.async.commit_group;");
}

// ---------------------------------------------------------------------------
// repack: W[cout, cinTot, 5, 5] -> PW[cg32][chunk][tap][pack2][lane32][slot4]
// ---------------------------------------------------------------------------
__global__ void repack_kernel(const float* __restrict__ W, float* __restrict__ PW,
                              int cinTot, int nChunks, int total) {
    int idx = blockIdx.x * 256 + threadIdx.x;
    if (idx >= total) return;
    int d       = idx % 6400;
    int cgchunk = idx / 6400;
    int chunk   = cgchunk % nChunks;
    int cg      = cgchunk / nChunks;
    int slot = d & 3;
    int lane = (d >> 2) & 31;
    int pack = (d >> 7) & 1;
    int tap  = d >> 8;
    int co = cg * 32 + pack * 16 + ((slot & 1) << 3) + (lane >> 2);
    int ci = chunk * 8 + (lane & 3) + ((slot >> 1) << 2);
    PW[idx] = to_tf32(W[((size_t)co * cinTot + ci) * 25 + tap]);
}

// ---------------------------------------------------------------------------
// padify: [planes,256] -> padded tf32 [planes,640] (20 rows x 32 cols, halo=0)
// ---------------------------------------------------------------------------
__global__ void padify_kernel(const float* __restrict__ src, float* __restrict__ dst,
                              int total) {
    int idx = blockIdx.x * 256 + threadIdx.x;
    if (idx >= total) return;
    int plane = idx / 640;
    int pp    = idx - plane * 640;
    int row = pp >> 5, col = pp & 31;
    float v = 0.f;
    if ((unsigned)(row - 2) < 16u && (unsigned)(col - 2) < 16u)
        v = to_tf32(src[plane * 256 + (row - 2) * 16 + (col - 2)]);
    dst[idx] = v;
}

// ---------------------------------------------------------------------------
struct Seg { const float* pad; int cin; int chunkBase; };
struct ConvArgs {
    Seg seg[4];
    int nseg;
    const float* PW;
    int nChunks;
    const float* bias;
    const float* base;
    float* out;
    int cout;
};

// buffer: weights 6400 floats + planes 8*648 = 5184 floats
#define BUF_FLOATS 11584
#define CONV_SMEM_BYTES (2 * BUF_FLOATS * 4)   // 92672

__global__ void __launch_bounds__(256, 2) conv5x5_mma_kernel(ConvArgs a) {
    extern __shared__ float smem[];

    const int b    = blockIdx.y;
    const int cg   = blockIdx.x;
    const int tid  = threadIdx.x;
    const int lane = tid & 31;
    const int warp = tid >> 5;
    const int tig  = lane & 3;
    const int g    = lane >> 2;

    int bB[4];
#pragma unroll
    for (int n = 0; n < 4; ++n) {
        int p  = warp * 32 + n * 8;
        bB[n] = (p >> 4) * 32 + (p & 15) + g;
    }

    float acc[2][4][4];
#pragma unroll
    for (int m = 0; m < 2; ++m)
#pragma unroll
        for (int n = 0; n < 4; ++n)
#pragma unroll
            for (int k = 0; k < 4; ++k) acc[m][n][k] = 0.f;

    int total = 0;
    for (int s = 0; s < a.nseg; ++s) total += a.seg[s].cin >> 3;

    const uint32_t smemBase = (uint32_t)__cvta_generic_to_shared(smem);

    // prefetch chunk (s,c8) into buffer bi
#define ISSUE(S, C8, BI) do {                                                   \
        const uint32_t dw = smemBase + (BI) * (BUF_FLOATS * 4);                 \
        const uint32_t dp = dw + 6400 * 4;                                      \
        const float* pw = a.PW +                                                \
            (size_t)(cg * a.nChunks + a.seg[S].chunkBase + (C8)) * 6400;        \
        for (int j = tid; j < 1600; j += 256)                                   \
            cpasync16(dw + j * 16, pw + j * 4);                                 \
        const float* sp = a.seg[S].pad +                                        \
            ((size_t)b * a.seg[S].cin + (C8) * 8) * 640;                        \
        for (int j = tid; j < 1280; j += 256) {                                 \
            int ci = j / 160, r = j - ci * 160;                                 \
            cpasync16(dp + ci * 2592 + r * 16, sp + ci * 640 + r * 4);          \
        }                                                                       \
    } while (0)

    int s = 0, c8 = 0;
    ISSUE(s, c8, 0);
    cpcommit();

    for (int i = 0; i < total; ++i) {
        int sn = s, cn = c8 + 1;
        if (cn == (a.seg[sn].cin >> 3)) { cn = 0; ++sn; }
        if (i + 1 < total) ISSUE(sn, cn, (i + 1) & 1);
        cpcommit();
        asm volatile("cp.async.wait_group 1;");
        __syncthreads();

        const float*  swb = smem + (i & 1) * BUF_FLOATS;
        const float*  plb = swb + 6400;
        const float4* swv = (const float4*)swb;
        const float*  pl0 = plb + tig * 648;
        const float*  pl1 = plb + (tig + 4) * 648;

#pragma unroll
        for (int dy = 0; dy < 5; ++dy) {
#pragma unroll
            for (int dx = 0; dx < 5; ++dx) {
                const int tap = dy * 5 + dx;
                const float4 A0 = swv[(tap * 2) * 32 + lane];
                const float4 A1 = swv[(tap * 2 + 1) * 32 + lane];
                const int off = dy * 32 + dx;
#pragma unroll
                for (int n = 0; n < 4; ++n) {
                    const float b0 = pl0[bB[n] + off];
                    const float b1 = pl1[bB[n] + off];
                    mma_tf32(acc[0][n][0], acc[0][n][1], acc[0][n][2], acc[0][n][3],
                             A0.x, A0.y, A0.z, A0.w, b0, b1);
                    mma_tf32(acc[1][n][0], acc[1][n][1], acc[1][n][2], acc[1][n][3],
                             A1.x, A1.y, A1.z, A1.w, b0, b1);
                }
            }
        }
        __syncthreads();
        s = sn; c8 = cn;
    }
#undef ISSUE

    // epilogue
    const int coBase = cg * 32;
#pragma unroll
    for (int m = 0; m < 2; ++m) {
        const int row0 = coBase + m * 16 + g;
        const int row1 = row0 + 8;
        const float bias0 = a.bias ? a.bias[row0] : 0.f;
        const float bias1 = a.bias ? a.bias[row1] : 0.f;
#pragma unroll
        for (int n = 0; n < 4; ++n) {
            const int col = warp * 32 + n * 8 + 2 * tig;
            size_t o0 = ((size_t)b * a.cout + row0) * PIX + col;
            size_t o1 = ((size_t)b * a.cout + row1) * PIX + col;
            float v0 = acc[m][n][0] + bias0;
            float v1 = acc[m][n][1] + bias0;
            float v2 = acc[m][n][2] + bias1;
            float v3 = acc[m][n][3] + bias1;
            if (a.base) {
                v0 += a.base[o0];     v1 += a.base[o0 + 1];
                v2 += a.base[o1];     v3 += a.base[o1 + 1];
            }
            a.out[o0]     = v0;
            a.out[o0 + 1] = v1;
            a.out[o1]     = v2;
            a.out[o1 + 1] = v3;
        }
    }
}

// ---------------------------------------------------------------------------
__device__ __forceinline__ float sigmoidf_(float x) { return 1.f / (1.f + expf(-x)); }

// h_exact may be null; h_pad is padded tf32 [B,128,640]
__global__ void lstm_kernel(const float* __restrict__ gates,
                            const float* __restrict__ c_in,
                            float* __restrict__ h_exact,
                            float* __restrict__ h_pad,
                            float* __restrict__ c_out) {
    int idx = blockIdx.x * blockDim.x + threadIdx.x;
    if (idx >= 4194304) return;
    int b = idx >> 15;
    int r = idx & 32767;
    size_t g0 = (size_t)b * 131072 + r;
    float ig = gates[g0];
    float fg = gates[g0 + 32768];
    float og = gates[g0 + 65536];
    float gg = gates[g0 + 98304];
    float c  = sigmoidf_(fg) * c_in[idx] + sigmoidf_(ig) * tanhf(gg);
    c_out[idx] = c;
    float h = sigmoidf_(og) * tanhf(c);
    if (h_exact) h_exact[idx] = h;
    int ch = r >> 8, pix = r & 255;
    int row = pix >> 4, col = pix & 15;
    h_pad[((size_t)(b * 128 + ch)) * 640 + (row + 2) * 32 + (col + 2)] = to_tf32(h);
}

// ---------------------------------------------------------------------------
__global__ void zkl_kernel(const float* __restrict__ rq,
                           const float* __restrict__ rp,
                           const float* __restrict__ eps_t,
                           float* __restrict__ z,
                           float* __restrict__ z_pad,
                           float* __restrict__ klb,
                           float* __restrict__ lpqb) {
    const int b = blockIdx.x;
    const int tid = threadIdx.x;
    const float* rqb = rq + (size_t)b * 32768;
    const float* rpb = rp + (size_t)b * 32768;
    const float* eb  = eps_t + (size_t)b * 16384;
    float* zb = z + (size_t)b * 16384;

    float kl = 0.f, lpq = 0.f;
    for (int i = tid; i < 16384; i += 256) {
        float mq = rqb[i], lq = rqb[i + 16384];
        float mp = rpb[i], lp = rpb[i + 16384];
        float e  = eb[i];
        float zi = mq + expf(0.5f * lq) * e;
        zb[i] = zi;
        int ch = i >> 8, pix = i & 255;
        int row = pix >> 4, col = pix & 15;
        z_pad[((size_t)(b * 64 + ch)) * 640 + (row + 2) * 32 + (col + 2)] = to_tf32(zi);
        float dq = zi - mq, dp = zi - mp;
        lpq += 0.5f * ((lq + dq * dq * expf(-lq)) - (lp + dp * dp * expf(-lp)));
        float dm = mq - mp;
        kl  += 0.5f * (lp - lq + (expf(lq) + dm * dm) * expf(-lp) - 1.f);
    }
    __shared__ float s1[256], s2[256];
    s1[tid] = kl; s2[tid] = lpq;
    __syncthreads();
    for (int o = 128; o > 0; o >>= 1) {
        if (tid < o) { s1[tid] += s1[tid + o]; s2[tid] += s2[tid + o]; }
        __syncthreads();
    }
    if (tid == 0) { klb[b] += s1[0]; lpqb[b] += s2[0]; }
}

// ---------------------------------------------------------------------------
__global__ void copy_kernel(const float* __restrict__ src, float* __restrict__ dst, int n) {
    int i = blockIdx.x * blockDim.x + threadIdx.x;
    if (i < n) dst[i] = src[i];
}

__global__ void finalize_kernel(const float* __restrict__ klb,
                                const float* __restrict__ lpqb,
                                float* __restrict__ out_kl,
                                float* __restrict__ out_lpq) {
    __shared__ float s[128];
    int t = threadIdx.x;
    s[t] = klb[t];
    out_lpq[t] = lpqb[t];
    __syncthreads();
    for (int o = 64; o > 0; o >>= 1) {
        if (t < o) s[t] += s[t + o];
        __syncthreads();
    }
    if (t == 0) out_kl[0] = s[0] / 128.f;
}

// ---------------------------------------------------------------------------
static void launch_conv(const Seg* segs, int nseg, const float* PW, int nChunks,
                        const float* bias, const float* base, float* out, int cout) {
    ConvArgs a;
    for (int i = 0; i < 4; ++i) { a.seg[i].pad = nullptr; a.seg[i].cin = 0; a.seg[i].chunkBase = 0; }
    for (int i = 0; i < nseg; ++i) a.seg[i] = segs[i];
    a.nseg = nseg; a.PW = PW; a.nChunks = nChunks;
    a.bias = bias; a.base = base; a.out = out; a.cout = cout;
    dim3 grid(cout / 32, BATCH);
    conv5x5_mma_kernel<<<grid, 256, CONV_SMEM_BYTES>>>(a);
}

static void launch_repack(const float* W, float* PW, int cinTot, int cout) {
    int nChunks = cinTot / 8;
    int total = (cout / 32) * nChunks * 6400;
    repack_kernel<<<(total + 255) / 256, 256>>>(W, PW, cinTot, nChunks, total);
}

static void launch_padify(const float* src, float* dst, int planes) {
    int total = planes * 640;
    padify_kernel<<<(total + 255) / 256, 256>>>(src, dst, total);
}

extern "C" void kernel_launch(void* const* d_in, const int* in_sizes, int n_in,
                              void* d_out, int out_size) {
    (void)in_sizes; (void)n_in; (void)out_size;
    const float* C_t    = (const float*)d_in[0];
    const float* D_t    = (const float*)d_in[1];
    const float* a_tmo  = (const float*)d_in[2];
    const float* s_tmo  = (const float*)d_in[3];
    const float* c_ssm_tmo = (const float*)d_in[4];
    const float* z_tmo  = (const float*)d_in[5];
    const float* eps    = (const float*)d_in[6];
    const float* W_ssm  = (const float*)d_in[7];
    const float* b_ssm  = (const float*)d_in[8];
    const float* W_p    = (const float*)d_in[9];
    const float* b_p    = (const float*)d_in[10];
    const float* W_q    = (const float*)d_in[11];
    const float* b_q    = (const float*)d_in[12];
    const float* W_rp   = (const float*)d_in[13];
    const float* b_rp   = (const float*)d_in[14];
    const float* W_rq   = (const float*)d_in[15];
    const float* b_rq   = (const float*)d_in[16];

    static int smem_set = -1;
    if (smem_set < 0) {
        cudaFuncSetAttribute(conv5x5_mma_kernel,
                             cudaFuncAttributeMaxDynamicSharedMemorySize, CONV_SMEM_BYTES);
        smem_set = 1;
    }

    float* S;
    cudaGetSymbolAddress((void**)&S, g_scratch);
    float* static_q = S + OFF_STATIC_Q;
    float* static_p = S + OFF_STATIC_P;
    float* gates    = S + OFF_GATES;
    float* cp = S + OFF_CP;
    float* cq = S + OFF_CQ;
    float* rq = S + OFF_RQ;
    float* rp = S + OFF_RP;
    float* zb = S + OFF_Z;
    float* klb  = S + OFF_KLB;
    float* lpqb = S + OFF_LPQB;
    float* pw_ssm = S + OFF_PW_SSM;
    float* pw_q   = S + OFF_PW_Q;
    float* pw_p   = S + OFF_PW_P;
    float* pw_rq  = S + OFF_PW_RQ;
    float* pw_rp  = S + OFF_PW_RP;
    float* pad_C    = S + OFF_PAD_C;
    float* pad_D    = S + OFF_PAD_D;
    float* pad_a    = S + OFF_PAD_A;
    float* pad_stmo = S + OFF_PAD_STMO;
    float* pad_ztmo = S + OFF_PAD_ZTMO;
    float* pad_st   = S + OFF_PAD_ST;
    float* pad_hp   = S + OFF_PAD_HP;
    float* pad_hq   = S + OFF_PAD_HQ;
    float* pad_zb   = S + OFF_PAD_ZB;

    float* out    = (float*)d_out;
    float* out_z  = out;
    float* out_s  = out + 2097152;
    float* out_c  = out + 6291456;
    float* out_kl = out + 10485760;
    float* out_lpq= out + 10485761;

    // zero states + accumulators + ALL padded state buffers (pad_st..pad_zb).
    // Full clear is required for call-to-call determinism: pad_hp/pad_hq are
    // read at step 0 and must be zero on EVERY call, not just the first.
    cudaMemsetAsync(cp,  0, (size_t)2 * 4194304 * sizeof(float));      // cp, cq
    cudaMemsetAsync(klb, 0, 256 * sizeof(float));
    cudaMemsetAsync(pad_st, 0, (size_t)PAD_STATE_FLOATS * sizeof(float));

    // repack weights + padify inputs
    launch_repack(W_ssm, pw_ssm, 328, 512);
    launch_repack(W_q,   pw_q,   520, 512);
    launch_repack(W_p,   pw_p,   456, 512);
    launch_repack(W_rq,  pw_rq,  128, 128);
    launch_repack(W_rp,  pw_rp,  128, 128);
    launch_padify(C_t,   pad_C,    128 * 128);
    launch_padify(D_t,   pad_D,    128 * 128);
    launch_padify(a_tmo, pad_a,    128 * 8);
    launch_padify(s_tmo, pad_stmo, 128 * 128);
    launch_padify(z_tmo, pad_ztmo, 128 * 64);

    // ---- SSM ConvLSTM: [z_tmo 0-7, C_t 8-23, a 24, s_tmo 25-40] / 41 chunks ----
    {
        Seg segs[4] = { {pad_ztmo, 64, 0}, {pad_C, 128, 8}, {pad_a, 8, 24}, {pad_stmo, 128, 25} };
        launch_conv(segs, 4, pw_ssm, 41, b_ssm, nullptr, gates, 512);
        lstm_kernel<<<16384, 256>>>(gates, c_ssm_tmo, out_s, pad_st, out_c);
    }

    // ---- static parts ----
    {
        // q: [hp 0-15, D_t 16-31, s_t 32-47, a 48, hq 49-64]
        Seg segs[3] = { {pad_D, 128, 16}, {pad_st, 128, 32}, {pad_a, 8, 48} };
        launch_conv(segs, 3, pw_q, 65, b_q, nullptr, static_q, 512);
    }
    {
        // p: [z 0-7, C_t 8-23, s_t 24-39, a 40, hp 41-56]
        Seg segs[3] = { {pad_C, 128, 8}, {pad_st, 128, 24}, {pad_a, 8, 40} };
        launch_conv(segs, 3, pw_p, 57, b_p, nullptr, static_p, 512);
    }

    for (int t = 0; t < STEPS; ++t) {
        {
            Seg segs[2] = { {pad_hp, 128, 0}, {pad_hq, 128, 49} };
            launch_conv(segs, 2, pw_q, 65, nullptr, static_q, gates, 512);
        }
        lstm_kernel<<<16384, 256>>>(gates, cq, nullptr, pad_hq, cq);

        {
            Seg segs[1] = { {pad_hq, 128, 0} };
            launch_conv(segs, 1, pw_rq, 16, b_rq, nullptr, rq, 128);
        }
        {
            Seg segs[1] = { {pad_hp, 128, 0} };
            launch_conv(segs, 1, pw_rp, 16, b_rp, nullptr, rp, 128);
        }

        zkl_kernel<<<128, 256>>>(rq, rp, eps + (size_t)t * 2097152, zb, pad_zb, klb, lpqb);

        {
            Seg segs[2] = { {pad_zb, 64, 0}, {pad_hp, 128, 41} };
            launch_conv(segs, 2, pw_p, 57, nullptr, static_p, gates, 512);
        }
        lstm_kernel<<<16384, 256>>>(gates, cp, nullptr, pad_hp, cp);
    }

    copy_kernel<<<(2097152 + 255) / 256, 256>>>(zb, out_z, 2097152);
    finalize_kernel<<<1, 128>>>(klb, lpqb, out_kl, out_lpq);
}